// round 8
// baseline (speedup 1.0000x reference)
#include <cuda_runtime.h>
#include <math.h>

// Problem constants
constexpr int kB = 256, kN = 1152, kD = 8, kO = 10, kE = 16;
constexpr int kOE = kO * kE;  // 160

// Tiling: block owns 8 n and half the batches (128), in 16 chunks of 8.
constexpr int kNL   = 8;
constexpr int kTH   = 320;        // tid = nl + 8*eg + 32*o  (warp == o)
constexpr int kGX   = kN / kNL;   // 144
constexpr int kGY   = 2;
constexpr int kBH   = kB / kGY;   // 128
constexpr int kCB   = 8;
constexpr int kNCH  = kBH / kCB;  // 16

// SMEM (floats)
constexpr int kUSd  = kBH;                    // 128
constexpr int kUSnl = kD * kUSd + 4;          // 1028
constexpr int kOffL = kNL * kUSnl;            // 8224 (16B-aligned: *4 bytes /16 ok)
constexpr int kLRow = 44;                     // per-b row stride: mult of 4 -> LDS.128 aligned
constexpr int kLSnl = kBH * kLRow + 4;        // 5636 (mod 32 == 4 -> nl bank tiling)
constexpr int kSmemFloats1 = kOffL + kNL * kLSnl;  // 53312
constexpr int kSmemBytes1  = kSmemFloats1 * 4;     // 213248 (< 227KB cap)
constexpr int kSmemBytes0  = kOffL * 4;            // 32896

typedef unsigned long long u64;

__device__ float g_part[(size_t)kGX * kB * kOE];  // 23.6 MB
__device__ float g_vsum[kB * kOE];

#define FMA2(d, a, b_) asm("fma.rn.f32x2 %0, %1, %2, %0;" : "+l"(d) : "l"(a), "l"(b_))
#define MUL2(d, a, b_) asm("mul.rn.f32x2 %0, %1, %2;" : "=l"(d) : "l"(a), "l"(b_))
#define ADD2(d, a, b_) asm("add.rn.f32x2 %0, %1, %2;" : "=l"(d) : "l"(a), "l"(b_))
#define PACK2(d, lo, hi) \
  asm("mov.b64 %0, {%1, %2};" : "=l"(d) : "r"(__float_as_uint(lo)), "r"(__float_as_uint(hi)))
#define UNPK2(lo, hi, v)                                                \
  do {                                                                  \
    unsigned _l, _h;                                                    \
    asm("mov.b64 {%0, %1}, %2;" : "=r"(_l), "=r"(_h) : "l"(v));         \
    lo = __uint_as_float(_l); hi = __uint_as_float(_h);                 \
  } while (0)

__global__ void noop_kernel() {}

// 4x4 u_ji tile (bias included) for one chunk; W pre-packed as u64.
__device__ __forceinline__ void compute_acc(
    u64 acc[4][4], const float* __restrict__ up, const u64 w2[kD][4], u64 bp)
{
#pragma unroll
  for (int k = 0; k < 4; k++)
#pragma unroll
    for (int j = 0; j < 4; j++) acc[k][j] = bp;
#pragma unroll
  for (int d = 0; d < kD; d++) {
    ulonglong2 ua = *(const ulonglong2*)(up + d * kUSd);      // b (0,1),(2,3)
    ulonglong2 ub = *(const ulonglong2*)(up + d * kUSd + 4);  // b (4,5),(6,7)
    FMA2(acc[0][0], ua.x, w2[d][0]); FMA2(acc[0][1], ua.x, w2[d][1]);
    FMA2(acc[0][2], ua.x, w2[d][2]); FMA2(acc[0][3], ua.x, w2[d][3]);
    FMA2(acc[1][0], ua.y, w2[d][0]); FMA2(acc[1][1], ua.y, w2[d][1]);
    FMA2(acc[1][2], ua.y, w2[d][2]); FMA2(acc[1][3], ua.y, w2[d][3]);
    FMA2(acc[2][0], ub.x, w2[d][0]); FMA2(acc[2][1], ub.x, w2[d][1]);
    FMA2(acc[2][2], ub.x, w2[d][2]); FMA2(acc[2][3], ub.x, w2[d][3]);
    FMA2(acc[3][0], ub.y, w2[d][0]); FMA2(acc[3][1], ub.y, w2[d][1]);
    FMA2(acc[3][2], ub.y, w2[d][2]); FMA2(acc[3][3], ub.y, w2[d][3]);
  }
}

// MODE 0: c uniform (0.1 folded into squash).  MODE 1: c = softmax_o(<u_ji, g_vsum>).
template <int MODE>
__global__ void __launch_bounds__(kTH, 1) pass_kernel(
    const float* __restrict__ u_i,
    const float* __restrict__ W,
    const float* __restrict__ bias)
{
  extern __shared__ float sm[];
  float* u_s = sm;             // [nl(1028)][d(128)][b]
  float* l_s = sm + kOffL;     // [nl(5636)][b(44)]: partials [o*4+eg], then c at [o]

  const int tid = threadIdx.x;
  const int nl  = tid & 7;
  const int eg  = (tid >> 3) & 3;
  const int o   = tid >> 5;
  const int n0  = blockIdx.x * kNL;
  const int bb0 = blockIdx.y * kBH;

  // ---- W slice + bias, pre-packed f32x2 ----
  u64 w2[kD][4];
  {
    const float* Wp = W + ((size_t)(n0 + nl) * kO + o) * (kD * kE) + eg * 4;
#pragma unroll
    for (int d = 0; d < kD; d++) {
      float4 w4 = *(const float4*)(Wp + d * kE);
      PACK2(w2[d][0], w4.x, w4.x); PACK2(w2[d][1], w4.y, w4.y);
      PACK2(w2[d][2], w4.z, w4.z); PACK2(w2[d][3], w4.w, w4.w);
    }
  }
  const float bv = bias[(n0 + nl) * kO + o];
  u64 bp; PACK2(bp, bv, bv);

  // ---- stage u once: [b][n][d] -> [nl][d][b_local] ----
  for (int i = tid; i < kBH * kNL * 2; i += kTH) {
    int b = i >> 4, nl2 = (i >> 1) & 7, h = i & 1;
    float4 t = *(const float4*)(u_i + ((size_t)(bb0 + b) * kN + n0 + nl2) * kD + h * 4);
    float* du = u_s + nl2 * kUSnl + h * 4 * kUSd + b;
    du[0] = t.x; du[kUSd] = t.y; du[2 * kUSd] = t.z; du[3 * kUSd] = t.w;
  }
  __syncthreads();

  const float* up_base = u_s + nl * kUSnl;
  const int mm = ((nl >> 2) & 1) * 8 + ((nl >> 1) & 1) * 4 + (nl & 1) * 2;
  const int kk = mm >> 2, j0 = mm & 3;

  if (MODE) {
    // ===== Phase A: per-eg partial logits for all chunks (no barriers) =====
    for (int ch = 0; ch < kNCH; ch++) {
      const int bc  = ch * kCB;
      const int bca = bb0 + bc;
      u64 acc[4][4];
      compute_acc(acc, up_base + bc, w2, bp);

      u64 ag[4] = {0ull, 0ull, 0ull, 0ull};
#pragma unroll
      for (int k = 0; k < 4; k++) {
        const float* vp0 = g_vsum + (size_t)(bca + 2 * k) * kOE + o * kE + eg * 4;
        float4 va = *(const float4*)vp0;
        float4 vb = *(const float4*)(vp0 + kOE);
        u64 vp;
        PACK2(vp, va.x, vb.x); FMA2(ag[k], acc[k][0], vp);
        PACK2(vp, va.y, vb.y); FMA2(ag[k], acc[k][1], vp);
        PACK2(vp, va.z, vb.z); FMA2(ag[k], acc[k][2], vp);
        PACK2(vp, va.w, vb.w); FMA2(ag[k], acc[k][3], vp);
      }
      // store raw eg-partials: [nl][b][o*4+eg]
      float* ar = l_s + nl * kLSnl + bc * kLRow + o * 4 + eg;
#pragma unroll
      for (int k = 0; k < 4; k++) {
        float lo, hi; UNPK2(lo, hi, ag[k]);
        ar[(2 * k) * kLRow]     = lo;
        ar[(2 * k + 1) * kLRow] = hi;
      }
    }
    __syncthreads();

    // ===== Phase B: sum eg-partials + softmax, write c into own row =====
    for (int r = tid; r < kNL * kBH; r += kTH) {
      float* row = l_s + (r >> 7) * kLSnl + (r & 127) * kLRow;
      float a[kO]; float ss = 0.f;
#pragma unroll
      for (int i = 0; i < kO; i++) {
        float4 p = *(const float4*)(row + i * 4);
        a[i] = __expf(p.x + p.y + p.z + p.w);
        ss += a[i];
      }
      float inv = 1.f / ss;
#pragma unroll
      for (int i = 0; i < kO; i++) row[i] = a[i] * inv;   // c at [o], own row
    }
    __syncthreads();
  }

  // ===== Phase C: weighted sum, nl reduce-scatter, store partials =====
  for (int ch = 0; ch < kNCH; ch++) {
    const int bc  = ch * kCB;
    const int bca = bb0 + bc;
    u64 acc[4][4];
    compute_acc(acc, up_base + bc, w2, bp);

    u64 v16[16];
    if (MODE) {
      const float* cp = l_s + nl * kLSnl + bc * kLRow + o;
#pragma unroll
      for (int k = 0; k < 4; k++) {
        u64 cpk; PACK2(cpk, cp[(2 * k) * kLRow], cp[(2 * k + 1) * kLRow]);
#pragma unroll
        for (int j = 0; j < 4; j++) MUL2(v16[k * 4 + j], acc[k][j], cpk);
      }
    } else {
#pragma unroll
      for (int k = 0; k < 4; k++)
#pragma unroll
        for (int j = 0; j < 4; j++) v16[k * 4 + j] = acc[k][j];
    }

    // reduce-scatter over nl (lane bits 0-2)
    u64 v8[8];
    {
      const bool sel = (nl >> 2) & 1;
#pragma unroll
      for (int i = 0; i < 8; i++) {
        u64 send = sel ? v16[i] : v16[8 + i];
        u64 recv = __shfl_xor_sync(0xffffffffu, send, 4);
        u64 keep = sel ? v16[8 + i] : v16[i];
        ADD2(v8[i], keep, recv);
      }
    }
    u64 v4[4];
    {
      const bool sel = (nl >> 1) & 1;
#pragma unroll
      for (int i = 0; i < 4; i++) {
        u64 send = sel ? v8[i] : v8[4 + i];
        u64 recv = __shfl_xor_sync(0xffffffffu, send, 2);
        u64 keep = sel ? v8[4 + i] : v8[i];
        ADD2(v4[i], keep, recv);
      }
    }
    u64 v2[2];
    {
      const bool sel = nl & 1;
#pragma unroll
      for (int i = 0; i < 2; i++) {
        u64 send = sel ? v4[i] : v4[2 + i];
        u64 recv = __shfl_xor_sync(0xffffffffu, send, 1);
        u64 keep = sel ? v4[2 + i] : v4[i];
        ADD2(v2[i], keep, recv);
      }
    }
    {
      float l0, h0, l1, h1;
      UNPK2(l0, h0, v2[0]); UNPK2(l1, h1, v2[1]);
      float* dp = &g_part[((size_t)blockIdx.x * kB + bca + 2 * kk) * kOE
                          + o * kE + eg * 4 + j0];
      *(float2*)dp         = make_float2(l0, l1);
      *(float2*)(dp + kOE) = make_float2(h0, h1);
    }
  }
}

// Reduce 144 partials (scaled) + squash; mode 0: vsum=v, 1: vsum+=v, 2: out=v.
__global__ void squash_kernel(float* __restrict__ out, int mode, float scale) {
  int gt = blockIdx.x * blockDim.x + threadIdx.x;
  if (gt >= kB * kO * 4) return;
  int eq = gt & 3, row = gt >> 2;
  const float* pp = g_part + (size_t)row * kE + eq * 4;
  float4 a = {0.f, 0.f, 0.f, 0.f};
#pragma unroll 4
  for (int p = 0; p < kGX; p++) {
    float4 t = *(const float4*)(pp + (size_t)p * kB * kOE);
    a.x += t.x; a.y += t.y; a.z += t.z; a.w += t.w;
  }
  a.x *= scale; a.y *= scale; a.z *= scale; a.w *= scale;
  float n2 = a.x * a.x + a.y * a.y + a.z * a.z + a.w * a.w;
  n2 += __shfl_xor_sync(0xffffffffu, n2, 1);
  n2 += __shfl_xor_sync(0xffffffffu, n2, 2);
  float f = sqrtf(n2) / (1.f + n2);
  float4 v = make_float4(a.x * f, a.y * f, a.z * f, a.w * f);
  if (mode == 2) {
    *(float4*)(out + (size_t)row * kE + eq * 4) = v;
  } else if (mode == 1) {
    float4 old = *(const float4*)(g_vsum + (size_t)row * kE + eq * 4);
    v.x += old.x; v.y += old.y; v.z += old.z; v.w += old.w;
    *(float4*)(g_vsum + (size_t)row * kE + eq * 4) = v;
  } else {
    *(float4*)(g_vsum + (size_t)row * kE + eq * 4) = v;
  }
}

extern "C" void kernel_launch(void* const* d_in, const int* in_sizes, int n_in,
                              void* d_out, int out_size) {
  const float* u    = (const float*)d_in[0];
  const float* W    = (const float*)d_in[1];
  const float* bias = (const float*)d_in[2];
  float* out = (float*)d_out;

  cudaFuncSetAttribute((const void*)pass_kernel<0>,
                       cudaFuncAttributeMaxDynamicSharedMemorySize, kSmemBytes0);
  cudaFuncSetAttribute((const void*)pass_kernel<1>,
                       cudaFuncAttributeMaxDynamicSharedMemorySize, kSmemBytes1);

  dim3 grid(kGX, kGY);  // 288 blocks, 1 CTA/SM

  noop_kernel<<<1, 32>>>();  // keeps ncu -s 5 -c 1 on the 2nd pass_kernel<1>

  pass_kernel<0><<<grid, kTH, kSmemBytes0>>>(u, W, bias);
  squash_kernel<<<40, 256>>>(nullptr, 0, 0.1f);

  pass_kernel<1><<<grid, kTH, kSmemBytes1>>>(u, W, bias);
  squash_kernel<<<40, 256>>>(nullptr, 1, 1.0f);

  pass_kernel<1><<<grid, kTH, kSmemBytes1>>>(u, W, bias);
  squash_kernel<<<40, 256>>>(out, 2, 1.0f);
}

// round 9
// speedup vs baseline: 1.0324x; 1.0324x over previous
#include <cuda_runtime.h>
#include <math.h>

// Problem constants
constexpr int kB = 256, kN = 1152, kD = 8, kO = 10, kE = 16;
constexpr int kOE = kO * kE;  // 160

// Tiling: block owns 4 n and half the batches (128), in 16 chunks of 8.
constexpr int kNL   = 4;
constexpr int kTH   = 160;        // tid = nl(b0-1) + eg(b2-3)*4 + o(b4+)*16
constexpr int kGX   = kN / kNL;   // 288
constexpr int kGY   = 2;
constexpr int kBH   = kB / kGY;   // 128
constexpr int kCB   = 8;
constexpr int kNCH  = kBH / kCB;  // 16

// SMEM (floats)
constexpr int kUSd  = kBH;                  // 128
constexpr int kUSnl = kD * kUSd + 4;        // 1028 (nl tiles banks by 4)
constexpr int kOffL = kNL * kUSnl;          // 4112
constexpr int kLSb  = kO;                   // 10
constexpr int kLSnl = kBH * kLSb + 4;       // 1284 (mod 32 == 4)
constexpr int kSmemFloats1 = kOffL + kNL * kLSnl;  // 9248
constexpr int kSmemBytes1  = kSmemFloats1 * 4;     // 36992 (4 CTAs: 148KB)
constexpr int kSmemBytes0  = kOffL * 4;            // 16448

typedef unsigned long long u64;

__device__ float g_part[(size_t)kGX * kB * kOE];  // 47.2 MB
__device__ float g_vsum[kB * kOE];

#define FMA2(d, a, b_) asm("fma.rn.f32x2 %0, %1, %2, %0;" : "+l"(d) : "l"(a), "l"(b_))
#define MUL2(d, a, b_) asm("mul.rn.f32x2 %0, %1, %2;" : "=l"(d) : "l"(a), "l"(b_))
#define ADD2(d, a, b_) asm("add.rn.f32x2 %0, %1, %2;" : "=l"(d) : "l"(a), "l"(b_))
#define PACK2(d, lo, hi) \
  asm("mov.b64 %0, {%1, %2};" : "=l"(d) : "r"(__float_as_uint(lo)), "r"(__float_as_uint(hi)))
#define UNPK2(lo, hi, v)                                                \
  do {                                                                  \
    unsigned _l, _h;                                                    \
    asm("mov.b64 {%0, %1}, %2;" : "=r"(_l), "=r"(_h) : "l"(v));         \
    lo = __uint_as_float(_l); hi = __uint_as_float(_h);                 \
  } while (0)

__global__ void noop_kernel() {}

// 4x4 u_ji tile (bias included) for one chunk.
__device__ __forceinline__ void compute_acc(
    u64 acc[4][4], const float* __restrict__ up, const float w[kD][4], u64 bp)
{
#pragma unroll
  for (int k = 0; k < 4; k++)
#pragma unroll
    for (int j = 0; j < 4; j++) acc[k][j] = bp;
#pragma unroll
  for (int d = 0; d < kD; d++) {
    ulonglong2 ua = *(const ulonglong2*)(up + d * kUSd);      // b (0,1),(2,3)
    ulonglong2 ub = *(const ulonglong2*)(up + d * kUSd + 4);  // b (4,5),(6,7)
    u64 w2[4];
    PACK2(w2[0], w[d][0], w[d][0]); PACK2(w2[1], w[d][1], w[d][1]);
    PACK2(w2[2], w[d][2], w[d][2]); PACK2(w2[3], w[d][3], w[d][3]);
    FMA2(acc[0][0], ua.x, w2[0]); FMA2(acc[0][1], ua.x, w2[1]);
    FMA2(acc[0][2], ua.x, w2[2]); FMA2(acc[0][3], ua.x, w2[3]);
    FMA2(acc[1][0], ua.y, w2[0]); FMA2(acc[1][1], ua.y, w2[1]);
    FMA2(acc[1][2], ua.y, w2[2]); FMA2(acc[1][3], ua.y, w2[3]);
    FMA2(acc[2][0], ub.x, w2[0]); FMA2(acc[2][1], ub.x, w2[1]);
    FMA2(acc[2][2], ub.x, w2[2]); FMA2(acc[2][3], ub.x, w2[3]);
    FMA2(acc[3][0], ub.y, w2[0]); FMA2(acc[3][1], ub.y, w2[1]);
    FMA2(acc[3][2], ub.y, w2[2]); FMA2(acc[3][3], ub.y, w2[3]);
  }
}

// MODE 0: c uniform (0.1 folded into squash).  MODE 1: c = softmax_o(<u_ji, g_vsum>).
template <int MODE>
__global__ void __launch_bounds__(kTH, 4) pass_kernel(
    const float* __restrict__ u_i,
    const float* __restrict__ W,
    const float* __restrict__ bias)
{
  extern __shared__ float sm[];
  float* u_s = sm;             // [nl(1028)][d(128)][b]
  float* l_s = sm + kOffL;     // [nl(1284)][b][o]  (MODE 1 only)

  const int tid = threadIdx.x;
  const int nl  = tid & 3;
  const int eg  = (tid >> 2) & 3;
  const int o   = tid >> 4;         // 0..9; warp covers 2 o's
  const int n0  = blockIdx.x * kNL;
  const int bb0 = blockIdx.y * kBH;

  // ---- W slice + bias (scalars; packed per chunk) ----
  float w[kD][4];
  {
    const float* Wp = W + ((size_t)(n0 + nl) * kO + o) * (kD * kE) + eg * 4;
#pragma unroll
    for (int d = 0; d < kD; d++) {
      float4 w4 = *(const float4*)(Wp + d * kE);
      w[d][0] = w4.x; w[d][1] = w4.y; w[d][2] = w4.z; w[d][3] = w4.w;
    }
  }
  const float bv = bias[(n0 + nl) * kO + o];
  u64 bp; PACK2(bp, bv, bv);

  // ---- stage u once: [b][n][d] -> [nl][d][b_local] ----
  for (int i = tid; i < kBH * kNL * 2; i += kTH) {
    int b = i >> 3, nl2 = (i >> 1) & 3, h = i & 1;
    float4 t = *(const float4*)(u_i + ((size_t)(bb0 + b) * kN + n0 + nl2) * kD + h * 4);
    float* du = u_s + nl2 * kUSnl + h * 4 * kUSd + b;
    du[0] = t.x; du[kUSd] = t.y; du[2 * kUSd] = t.z; du[3 * kUSd] = t.w;
  }
  __syncthreads();

  const float* up_base = u_s + nl * kUSnl;

  if (MODE) {
    // ===== Phase A: logits for all chunks (no barriers inside) =====
    for (int ch = 0; ch < kNCH; ch++) {
      const int bc  = ch * kCB;
      const int bca = bb0 + bc;
      u64 acc[4][4];
      compute_acc(acc, up_base + bc, w, bp);

      u64 ag[4] = {0ull, 0ull, 0ull, 0ull};
#pragma unroll
      for (int k = 0; k < 4; k++) {
        const float* vp0 = g_vsum + (size_t)(bca + 2 * k) * kOE + o * kE + eg * 4;
        float4 va = *(const float4*)vp0;
        float4 vb = *(const float4*)(vp0 + kOE);
        u64 vp;
        PACK2(vp, va.x, vb.x); FMA2(ag[k], acc[k][0], vp);
        PACK2(vp, va.y, vb.y); FMA2(ag[k], acc[k][1], vp);
        PACK2(vp, va.z, vb.z); FMA2(ag[k], acc[k][2], vp);
        PACK2(vp, va.w, vb.w); FMA2(ag[k], acc[k][3], vp);
      }
      // reduce over eg (lane bits 2,3)
      float al[4], ah[4];
#pragma unroll
      for (int k = 0; k < 4; k++) {
        UNPK2(al[k], ah[k], ag[k]);
        al[k] += __shfl_xor_sync(0xffffffffu, al[k], 4);
        al[k] += __shfl_xor_sync(0xffffffffu, al[k], 8);
        ah[k] += __shfl_xor_sync(0xffffffffu, ah[k], 4);
        ah[k] += __shfl_xor_sync(0xffffffffu, ah[k], 8);
      }
      if (eg == 0) {
        float* ar = l_s + nl * kLSnl + bc * kLSb + o;
#pragma unroll
        for (int k = 0; k < 4; k++) {
          ar[(2 * k) * kLSb]     = al[k];
          ar[(2 * k + 1) * kLSb] = ah[k];
        }
      }
    }
    __syncthreads();

    // ===== Phase B: softmax over o for all 512 (nl, b) rows =====
    for (int r = tid; r < kNL * kBH; r += kTH) {
      float* row = l_s + (r >> 7) * kLSnl + (r & 127) * kLSb;
      float a[kO]; float ss = 0.f;
#pragma unroll
      for (int i = 0; i < kO; i++) { a[i] = __expf(row[i]); ss += a[i]; }
      float inv = 1.f / ss;
#pragma unroll
      for (int i = 0; i < kO; i++) row[i] = a[i] * inv;
    }
    __syncthreads();
  }

  // ===== Phase C: weighted sum, nl reduce-scatter, store partials =====
  for (int ch = 0; ch < kNCH; ch++) {
    const int bc  = ch * kCB;
    const int bca = bb0 + bc;
    u64 acc[4][4];
    compute_acc(acc, up_base + bc, w, bp);

    u64 v16[16];
    if (MODE) {
      const float* cp = l_s + nl * kLSnl + bc * kLSb + o;
#pragma unroll
      for (int k = 0; k < 4; k++) {
        u64 cpk; PACK2(cpk, cp[(2 * k) * kLSb], cp[(2 * k + 1) * kLSb]);
#pragma unroll
        for (int j = 0; j < 4; j++) MUL2(v16[k * 4 + j], acc[k][j], cpk);
      }
    } else {
#pragma unroll
      for (int k = 0; k < 4; k++)
#pragma unroll
        for (int j = 0; j < 4; j++) v16[k * 4 + j] = acc[k][j];
    }

    // reduce-scatter over nl (lane bits 0,1): 2 levels
    u64 v8[8];
    {
      const bool sel = (nl >> 1) & 1;
#pragma unroll
      for (int i = 0; i < 8; i++) {
        u64 send = sel ? v16[i] : v16[8 + i];
        u64 recv = __shfl_xor_sync(0xffffffffu, send, 2);
        u64 keep = sel ? v16[8 + i] : v16[i];
        ADD2(v8[i], keep, recv);
      }
    }
    u64 v4[4];
    {
      const bool sel = nl & 1;
#pragma unroll
      for (int i = 0; i < 4; i++) {
        u64 send = sel ? v8[i] : v8[4 + i];
        u64 recv = __shfl_xor_sync(0xffffffffu, send, 1);
        u64 keep = sel ? v8[4 + i] : v8[i];
        ADD2(v4[i], keep, recv);
      }
    }

    // lane holds batch-pair k = nl, e-offsets j=0..3 (lo=batch 2k, hi=2k+1)
    {
      float l0, h0, l1, h1, l2, h2, l3, h3;
      UNPK2(l0, h0, v4[0]); UNPK2(l1, h1, v4[1]);
      UNPK2(l2, h2, v4[2]); UNPK2(l3, h3, v4[3]);
      float* dp = &g_part[((size_t)blockIdx.x * kB + bca + 2 * nl) * kOE
                          + o * kE + eg * 4];
      *(float4*)dp         = make_float4(l0, l1, l2, l3);
      *(float4*)(dp + kOE) = make_float4(h0, h1, h2, h3);
    }
  }
}

// Reduce 288 partials (split over lane pairs) + squash.
__global__ void squash_kernel(float* __restrict__ out, int mode, float scale) {
  int gt = blockIdx.x * blockDim.x + threadIdx.x;
  if (gt >= kB * kO * 4 * 2) return;           // 20480
  int h = gt & 1, eq = (gt >> 1) & 3, row = gt >> 3;   // row = b*10 + o
  int b = row / 10, oo = row - b * 10;
  const float* pp = g_part + (size_t)b * kOE + oo * kE + eq * 4
                  + (size_t)(h * 144) * kB * kOE;
  float4 a = {0.f, 0.f, 0.f, 0.f};
#pragma unroll 4
  for (int p = 0; p < 144; p++) {
    float4 t = *(const float4*)(pp + (size_t)p * kB * kOE);
    a.x += t.x; a.y += t.y; a.z += t.z; a.w += t.w;
  }
  // combine p-halves (lane bit 0)
  a.x += __shfl_xor_sync(0xffffffffu, a.x, 1);
  a.y += __shfl_xor_sync(0xffffffffu, a.y, 1);
  a.z += __shfl_xor_sync(0xffffffffu, a.z, 1);
  a.w += __shfl_xor_sync(0xffffffffu, a.w, 1);
  a.x *= scale; a.y *= scale; a.z *= scale; a.w *= scale;
  float n2 = a.x * a.x + a.y * a.y + a.z * a.z + a.w * a.w;
  n2 += __shfl_xor_sync(0xffffffffu, n2, 2);
  n2 += __shfl_xor_sync(0xffffffffu, n2, 4);
  float f = sqrtf(n2) / (1.f + n2);
  float4 v = make_float4(a.x * f, a.y * f, a.z * f, a.w * f);
  if (h == 0) {
    if (mode == 2) {
      *(float4*)(out + (size_t)row * kE + eq * 4) = v;
    } else if (mode == 1) {
      float4 old = *(const float4*)(g_vsum + (size_t)row * kE + eq * 4);
      v.x += old.x; v.y += old.y; v.z += old.z; v.w += old.w;
      *(float4*)(g_vsum + (size_t)row * kE + eq * 4) = v;
    } else {
      *(float4*)(g_vsum + (size_t)row * kE + eq * 4) = v;
    }
  }
}

extern "C" void kernel_launch(void* const* d_in, const int* in_sizes, int n_in,
                              void* d_out, int out_size) {
  const float* u    = (const float*)d_in[0];
  const float* W    = (const float*)d_in[1];
  const float* bias = (const float*)d_in[2];
  float* out = (float*)d_out;

  dim3 grid(kGX, kGY);  // 576 blocks, 4 CTAs/SM

  noop_kernel<<<1, 32>>>();  // keeps ncu -s 5 -c 1 on the 2nd pass_kernel<1>

  pass_kernel<0><<<grid, kTH, kSmemBytes0>>>(u, W, bias);
  squash_kernel<<<80, 256>>>(nullptr, 0, 0.1f);

  pass_kernel<1><<<grid, kTH, kSmemBytes1>>>(u, W, bias);
  squash_kernel<<<80, 256>>>(nullptr, 1, 1.0f);

  pass_kernel<1><<<grid, kTH, kSmemBytes1>>>(u, W, bias);
  squash_kernel<<<80, 256>>>(out, 2, 1.0f);
}